// round 2
// baseline (speedup 1.0000x reference)
#include <cuda_runtime.h>
#include <math.h>

#define NN 50000
#define EE 800000
#define CC 16
#define MM 32
#define GG 8

// Padded table strides (floats) to avoid shared-mem bank conflicts on
// vectorized loads: bank spread comes from the c/i index after padding.
#define BSTRIDE 260   // per-c stride for B tables: c*260 + m*8 + g   (260%32=4)
#define QSTRIDE 132   // per-i stride for Q table:  i*132 + l*8 + g   (132%32=4)

// ---------------- device scratch (static: no allocations allowed) ----------
__device__ float  g_smB0[CC * BSTRIDE];
__device__ float  g_smB1[CC * BSTRIDE];
__device__ float  g_smQ [CC * QSTRIDE];
__device__ float  g_smPi[CC * GG];
__device__ float4 g_post0[NN * 32];       // post0[n][c][g] as 32 float4 per node
__device__ int    g_cnt[NN];
__device__ int    g_off[NN + 1];
__device__ int    g_cur[NN];
__device__ int    g_csr[EE];

// ---------------- K0: softmaxes of the tiny parameter tables ---------------
__global__ void softmax_k(const float* __restrict__ B0, const float* __restrict__ Pi,
                          const float* __restrict__ B1, const float* __restrict__ Q) {
    int t = threadIdx.x;            // 128 threads
    int c = t >> 3, g = t & 7;

    // B0: softmax over m (axis 1) for each (c,g)
    {
        float mx = -1e30f;
        #pragma unroll
        for (int m = 0; m < MM; m++) mx = fmaxf(mx, B0[(c * MM + m) * GG + g]);
        float e[MM]; float s = 0.f;
        #pragma unroll
        for (int m = 0; m < MM; m++) { e[m] = __expf(B0[(c * MM + m) * GG + g] - mx); s += e[m]; }
        float inv = 1.0f / s;
        #pragma unroll
        for (int m = 0; m < MM; m++) g_smB0[c * BSTRIDE + m * 8 + g] = e[m] * inv;
    }
    // B1: same shape/axis
    {
        float mx = -1e30f;
        #pragma unroll
        for (int m = 0; m < MM; m++) mx = fmaxf(mx, B1[(c * MM + m) * GG + g]);
        float e[MM]; float s = 0.f;
        #pragma unroll
        for (int m = 0; m < MM; m++) { e[m] = __expf(B1[(c * MM + m) * GG + g] - mx); s += e[m]; }
        float inv = 1.0f / s;
        #pragma unroll
        for (int m = 0; m < MM; m++) g_smB1[c * BSTRIDE + m * 8 + g] = e[m] * inv;
    }
    // Q_neigh: softmax over i (axis 0) for each (l,g); here l = c
    {
        int l = c;
        float mx = -1e30f;
        #pragma unroll
        for (int i = 0; i < CC; i++) mx = fmaxf(mx, Q[(i * CC + l) * GG + g]);
        float e[CC]; float s = 0.f;
        #pragma unroll
        for (int i = 0; i < CC; i++) { e[i] = __expf(Q[(i * CC + l) * GG + g] - mx); s += e[i]; }
        float inv = 1.0f / s;
        #pragma unroll
        for (int i = 0; i < CC; i++) g_smQ[i * QSTRIDE + l * 8 + g] = e[i] * inv;
    }
    // Pi: softmax over c (axis 0) per g  (threads 0..7)
    if (t < GG) {
        int gg = t;
        float mx = -1e30f;
        #pragma unroll
        for (int cc = 0; cc < CC; cc++) mx = fmaxf(mx, Pi[cc * GG + gg]);
        float e[CC]; float s = 0.f;
        #pragma unroll
        for (int cc = 0; cc < CC; cc++) { e[cc] = __expf(Pi[cc * GG + gg] - mx); s += e[cc]; }
        float inv = 1.0f / s;
        #pragma unroll
        for (int cc = 0; cc < CC; cc++) g_smPi[cc * GG + gg] = e[cc] * inv;
    }
}

// ---------------- K1: zero degree counters ---------------------------------
__global__ void zero_k() {
    int i = blockIdx.x * blockDim.x + threadIdx.x;
    if (i < NN) g_cnt[i] = 0;
}

// ---------------- K2: out-degree histogram ---------------------------------
__global__ void count_k(const int* __restrict__ ei) {
    int e = blockIdx.x * blockDim.x + threadIdx.x;
    if (e < EE) atomicAdd(&g_cnt[ei[e]], 1);   // src = ei[0..E)
}

// ---------------- K3: single-block exclusive scan -> CSR offsets -----------
__global__ void scan_k() {
    __shared__ int part[1024];
    const int t = threadIdx.x;
    const int CH = (NN + 1023) >> 10;          // 49
    int st = t * CH, en = min(st + CH, NN);
    int s = 0;
    for (int i = st; i < en; i++) s += g_cnt[i];
    part[t] = s;
    __syncthreads();
    for (int off = 1; off < 1024; off <<= 1) {
        int v = (t >= off) ? part[t - off] : 0;
        __syncthreads();
        part[t] += v;
        __syncthreads();
    }
    int run = part[t] - s;                      // exclusive base
    for (int i = st; i < en; i++) {
        g_off[i] = run;
        g_cur[i] = run;
        run += g_cnt[i];
    }
    if (t == 1023) g_off[NN] = part[1023];
}

// ---------------- K4: scatter edges into CSR buckets ------------------------
__global__ void scatter_k(const int* __restrict__ ei) {
    int e = blockIdx.x * blockDim.x + threadIdx.x;
    if (e < EE) {
        int s = ei[e];
        int d = ei[EE + e];
        int pos = atomicAdd(&g_cur[s], 1);
        g_csr[pos] = d;
    }
}

// ---------------- K5: layer 0 — post0 + ll0 (warp per node) -----------------
__global__ __launch_bounds__(256) void layer0_k(const int* __restrict__ x,
                                                float* __restrict__ out) {
    __shared__ float sB0[CC * BSTRIDE];
    __shared__ float sPi[CC * GG];
    __shared__ __align__(16) float sbuf[8][136];
    for (int i = threadIdx.x; i < CC * BSTRIDE; i += 256) sB0[i] = g_smB0[i];
    for (int i = threadIdx.x; i < CC * GG;      i += 256) sPi[i] = g_smPi[i];
    __syncthreads();

    const int lane = threadIdx.x & 31;
    const int w    = threadIdx.x >> 5;
    const int node = blockIdx.x * 8 + w;       // N = 6250*8 exactly

    const int m  = x[node];
    const int c  = lane >> 1;
    const int g0 = (lane & 1) * 4;

    float4 b  = *(const float4*)&sB0[c * BSTRIDE + m * 8 + g0];
    float4 pi = *(const float4*)&sPi[c * 8 + g0];
    float4 u;
    u.x = b.x * pi.x; u.y = b.y * pi.y; u.z = b.z * pi.z; u.w = b.w * pi.w;

    *(float4*)&sbuf[w][lane * 4] = u;
    __syncwarp();
    if (lane < 8) {
        float s = 0.f;
        #pragma unroll
        for (int i = 0; i < CC; i++) s += sbuf[w][i * 8 + lane];
        out[node * 16 + lane] = logf(s);       // ll0: [n][0][g]
        sbuf[w][128 + lane] = 1.0f / s;
    }
    __syncwarp();
    float4 inv = *(const float4*)&sbuf[w][128 + g0];
    float4 p;
    p.x = u.x * inv.x; p.y = u.y * inv.y; p.z = u.z * inv.z; p.w = u.w * inv.w;
    g_post0[node * 32 + lane] = p;
}

// ---------------- K6: aggregation + layer 1 (warp per node) -----------------
__global__ __launch_bounds__(256) void layer1_k(const int* __restrict__ x,
                                                float* __restrict__ out) {
    __shared__ float sQ [CC * QSTRIDE];
    __shared__ float sB1[CC * BSTRIDE];
    __shared__ __align__(16) float sbuf[8][136];
    for (int i = threadIdx.x; i < CC * QSTRIDE; i += 256) sQ[i]  = g_smQ[i];
    for (int i = threadIdx.x; i < CC * BSTRIDE; i += 256) sB1[i] = g_smB1[i];
    __syncthreads();

    const int lane = threadIdx.x & 31;
    const int w    = threadIdx.x >> 5;
    const int node = blockIdx.x * 8 + w;

    // ---- scatter-mean: gather post0[dst] over this node's CSR list ----
    const int r0 = g_off[node], r1 = g_off[node + 1];
    float4 a0 = {0.f, 0.f, 0.f, 0.f};
    float4 a1 = {0.f, 0.f, 0.f, 0.f};
    int j = r0;
    for (; j + 3 < r1; j += 4) {
        int d0 = g_csr[j], d1 = g_csr[j + 1], d2 = g_csr[j + 2], d3 = g_csr[j + 3];
        float4 v0 = g_post0[d0 * 32 + lane];
        float4 v1 = g_post0[d1 * 32 + lane];
        float4 v2 = g_post0[d2 * 32 + lane];
        float4 v3 = g_post0[d3 * 32 + lane];
        a0.x += v0.x; a0.y += v0.y; a0.z += v0.z; a0.w += v0.w;
        a1.x += v1.x; a1.y += v1.y; a1.z += v1.z; a1.w += v1.w;
        a0.x += v2.x; a0.y += v2.y; a0.z += v2.z; a0.w += v2.w;
        a1.x += v3.x; a1.y += v3.y; a1.z += v3.z; a1.w += v3.w;
    }
    for (; j < r1; j++) {
        float4 v = g_post0[g_csr[j] * 32 + lane];
        a0.x += v.x; a0.y += v.y; a0.z += v.z; a0.w += v.w;
    }
    float inv_deg = 1.0f / fmaxf((float)(r1 - r0), 1.0f);
    float4 ag;
    ag.x = (a0.x + a1.x) * inv_deg;
    ag.y = (a0.y + a1.y) * inv_deg;
    ag.z = (a0.z + a1.z) * inv_deg;
    ag.w = (a0.w + a1.w) * inv_deg;

    *(float4*)&sbuf[w][lane * 4] = ag;         // aggr[l][g] in shared
    __syncwarp();

    // ---- layer 1: S[i,g] = sum_l Q[i,l,g]*aggr[l,g]; post1 = B*S/norm ----
    const int m  = x[node];
    const int i  = lane >> 1;
    const int g0 = (lane & 1) * 4;

    float4 S = {0.f, 0.f, 0.f, 0.f};
    const float* qrow = &sQ[i * QSTRIDE + g0];
    const float* arow = &sbuf[w][g0];
    #pragma unroll
    for (int l = 0; l < CC; l++) {
        float4 q = *(const float4*)(qrow + l * 8);
        float4 a = *(const float4*)(arow + l * 8);
        S.x += q.x * a.x; S.y += q.y * a.y; S.z += q.z * a.z; S.w += q.w * a.w;
    }
    float4 Bn = *(const float4*)&sB1[i * BSTRIDE + m * 8 + g0];
    float4 p;
    p.x = Bn.x * S.x; p.y = Bn.y * S.y; p.z = Bn.z * S.z; p.w = Bn.w * S.w;

    __syncwarp();                               // aggr reads done before overwrite
    *(float4*)&sbuf[w][lane * 4] = p;
    __syncwarp();
    if (lane < 8) {
        float s = 0.f;
        #pragma unroll
        for (int ii = 0; ii < CC; ii++) s += sbuf[w][ii * 8 + lane];
        out[node * 16 + 8 + lane] = logf(s);   // ll1: [n][1][g]
        sbuf[w][128 + lane] = 1.0f / s;
    }
    __syncwarp();
    float4 invn = *(const float4*)&sbuf[w][128 + g0];
    float4 o;
    o.x = p.x * invn.x; o.y = p.y * invn.y; o.z = p.z * invn.z; o.w = p.w * invn.w;
    ((float4*)(out + NN * 16 + node * 128))[lane] = o;   // post1
}

// ---------------- launch ----------------------------------------------------
extern "C" void kernel_launch(void* const* d_in, const int* in_sizes, int n_in,
                              void* d_out, int out_size) {
    const int*   x  = (const int*)d_in[0];
    const int*   ei = (const int*)d_in[1];
    const float* B0 = (const float*)d_in[2];
    const float* Pi = (const float*)d_in[3];
    const float* B1 = (const float*)d_in[4];
    const float* Q  = (const float*)d_in[5];
    float* out = (float*)d_out;

    softmax_k<<<1, 128>>>(B0, Pi, B1, Q);
    zero_k<<<(NN + 255) / 256, 256>>>();
    count_k<<<(EE + 255) / 256, 256>>>(ei);
    scan_k<<<1, 1024>>>();
    scatter_k<<<(EE + 255) / 256, 256>>>(ei);
    layer0_k<<<NN / 8, 256>>>(x, out);
    layer1_k<<<NN / 8, 256>>>(x, out);
}

// round 4
// speedup vs baseline: 1.5204x; 1.5204x over previous
#include <cuda_runtime.h>
#include <math.h>

#define NN 50000
#define EE 800000
#define CC 16
#define MM 32
#define GG 8
#define NB 49           // ceil(NN/1024) scan blocks

// Padded table strides (floats) to avoid shared-mem bank conflicts on
// vectorized loads: bank spread comes from the c/i index after padding.
#define BSTRIDE 260   // per-c stride for B tables: c*260 + m*8 + g   (260%32=4)
#define QSTRIDE 132   // per-i stride for Q table:  i*132 + l*8 + g   (132%32=4)

// ---------------- device scratch (static: no allocations allowed) ----------
__device__ float  g_smB0[CC * BSTRIDE];
__device__ float  g_smB1[CC * BSTRIDE];
__device__ float  g_smQ [CC * QSTRIDE];
__device__ float  g_smPi[CC * GG];
__device__ float4 g_post0[NN * 32];       // post0[n][c][g] as 32 float4 per node
__device__ int    g_cnt[NN];
__device__ int    g_off[NN + 1];
__device__ int    g_cur[NN];
__device__ int    g_csr[EE];
__device__ int    g_bsum[NB];
__device__ int    g_boff[NB];

// ---------------- K0: softmaxes of the tiny parameter tables ---------------
__global__ void softmax_k(const float* __restrict__ B0, const float* __restrict__ Pi,
                          const float* __restrict__ B1, const float* __restrict__ Q) {
    int t = threadIdx.x;            // 128 threads
    int c = t >> 3, g = t & 7;

    // B0: softmax over m (axis 1) for each (c,g)
    {
        float mx = -1e30f;
        #pragma unroll
        for (int m = 0; m < MM; m++) mx = fmaxf(mx, B0[(c * MM + m) * GG + g]);
        float e[MM]; float s = 0.f;
        #pragma unroll
        for (int m = 0; m < MM; m++) { e[m] = __expf(B0[(c * MM + m) * GG + g] - mx); s += e[m]; }
        float inv = 1.0f / s;
        #pragma unroll
        for (int m = 0; m < MM; m++) g_smB0[c * BSTRIDE + m * 8 + g] = e[m] * inv;
    }
    // B1: same shape/axis
    {
        float mx = -1e30f;
        #pragma unroll
        for (int m = 0; m < MM; m++) mx = fmaxf(mx, B1[(c * MM + m) * GG + g]);
        float e[MM]; float s = 0.f;
        #pragma unroll
        for (int m = 0; m < MM; m++) { e[m] = __expf(B1[(c * MM + m) * GG + g] - mx); s += e[m]; }
        float inv = 1.0f / s;
        #pragma unroll
        for (int m = 0; m < MM; m++) g_smB1[c * BSTRIDE + m * 8 + g] = e[m] * inv;
    }
    // Q_neigh: softmax over i (axis 0) for each (l,g); here l = c
    {
        int l = c;
        float mx = -1e30f;
        #pragma unroll
        for (int i = 0; i < CC; i++) mx = fmaxf(mx, Q[(i * CC + l) * GG + g]);
        float e[CC]; float s = 0.f;
        #pragma unroll
        for (int i = 0; i < CC; i++) { e[i] = __expf(Q[(i * CC + l) * GG + g] - mx); s += e[i]; }
        float inv = 1.0f / s;
        #pragma unroll
        for (int i = 0; i < CC; i++) g_smQ[i * QSTRIDE + l * 8 + g] = e[i] * inv;
    }
    // Pi: softmax over c (axis 0) per g  (threads 0..7)
    if (t < GG) {
        int gg = t;
        float mx = -1e30f;
        #pragma unroll
        for (int cc = 0; cc < CC; cc++) mx = fmaxf(mx, Pi[cc * GG + gg]);
        float e[CC]; float s = 0.f;
        #pragma unroll
        for (int cc = 0; cc < CC; cc++) { e[cc] = __expf(Pi[cc * GG + gg] - mx); s += e[cc]; }
        float inv = 1.0f / s;
        #pragma unroll
        for (int cc = 0; cc < CC; cc++) g_smPi[cc * GG + gg] = e[cc] * inv;
    }
}

// ---------------- K1: zero degree counters ---------------------------------
__global__ void zero_k() {
    int i = blockIdx.x * blockDim.x + threadIdx.x;
    if (i < NN) g_cnt[i] = 0;
}

// ---------------- K2: out-degree histogram ---------------------------------
__global__ void count_k(const int* __restrict__ ei) {
    int e = blockIdx.x * blockDim.x + threadIdx.x;
    if (e < EE) atomicAdd(&g_cnt[e < EE ? ei[e] : 0], 1);   // src = ei[0..E)
}

// ---------------- K3a: per-block sums of g_cnt ------------------------------
__global__ __launch_bounds__(1024) void bsum_k() {
    __shared__ int ws[32];
    int i = blockIdx.x * 1024 + threadIdx.x;
    int v = (i < NN) ? g_cnt[i] : 0;
    int r = __reduce_add_sync(0xffffffffu, v);
    int lane = threadIdx.x & 31, wid = threadIdx.x >> 5;
    if (lane == 0) ws[wid] = r;
    __syncthreads();
    if (wid == 0) {
        int s = ws[lane];
        s = __reduce_add_sync(0xffffffffu, s);
        if (lane == 0) g_bsum[blockIdx.x] = s;
    }
}

// ---------------- K3b: tiny scan of the NB block sums -----------------------
__global__ void bscan_k() {
    __shared__ int sh[64];
    int t = threadIdx.x;                       // 64 threads
    int v = (t < NB) ? g_bsum[t] : 0;
    sh[t] = v;
    __syncthreads();
    #pragma unroll
    for (int o = 1; o < 64; o <<= 1) {
        int tv = (t >= o) ? sh[t - o] : 0;
        __syncthreads();
        sh[t] += tv;
        __syncthreads();
    }
    int incl = sh[t];
    if (t < NB) g_boff[t] = incl - v;          // exclusive block offset
    if (t == NB - 1) g_off[NN] = incl;         // grand total
}

// ---------------- K3c: block-local scan + offset -> g_off/g_cur -------------
__global__ __launch_bounds__(1024) void scan2_k() {
    __shared__ int ws[32];
    int i = blockIdx.x * 1024 + threadIdx.x;
    int lane = threadIdx.x & 31, wid = threadIdx.x >> 5;
    int v = (i < NN) ? g_cnt[i] : 0;
    // warp inclusive scan
    int s = v;
    #pragma unroll
    for (int o = 1; o < 32; o <<= 1) {
        int t = __shfl_up_sync(0xffffffffu, s, o);
        if (lane >= o) s += t;
    }
    if (lane == 31) ws[wid] = s;
    __syncthreads();
    if (wid == 0) {
        int w = ws[lane];
        #pragma unroll
        for (int o = 1; o < 32; o <<= 1) {
            int t = __shfl_up_sync(0xffffffffu, w, o);
            if (lane >= o) w += t;
        }
        ws[lane] = w;
    }
    __syncthreads();
    int base = g_boff[blockIdx.x] + (wid > 0 ? ws[wid - 1] : 0);
    int excl = base + s - v;
    if (i < NN) { g_off[i] = excl; g_cur[i] = excl; }
}

// ---------------- K4: scatter edges into CSR buckets ------------------------
__global__ void scatter_k(const int* __restrict__ ei) {
    int e = blockIdx.x * blockDim.x + threadIdx.x;
    if (e < EE) {
        int s = ei[e];
        int d = ei[EE + e];
        int pos = atomicAdd(&g_cur[s], 1);
        g_csr[pos] = d;
    }
}

// ---------------- K5: layer 0 — post0 + ll0 (warp per node) -----------------
__global__ __launch_bounds__(256) void layer0_k(const int* __restrict__ x,
                                                float* __restrict__ out) {
    __shared__ float sB0[CC * BSTRIDE];
    __shared__ float sPi[CC * GG];
    __shared__ __align__(16) float sbuf[8][136];
    for (int i = threadIdx.x; i < CC * BSTRIDE; i += 256) sB0[i] = g_smB0[i];
    for (int i = threadIdx.x; i < CC * GG;      i += 256) sPi[i] = g_smPi[i];
    __syncthreads();

    const int lane = threadIdx.x & 31;
    const int w    = threadIdx.x >> 5;
    const int node = blockIdx.x * 8 + w;       // N = 6250*8 exactly

    const int m  = x[node];
    const int c  = lane >> 1;
    const int g0 = (lane & 1) * 4;

    float4 b  = *(const float4*)&sB0[c * BSTRIDE + m * 8 + g0];
    float4 pi = *(const float4*)&sPi[c * 8 + g0];
    float4 u;
    u.x = b.x * pi.x; u.y = b.y * pi.y; u.z = b.z * pi.z; u.w = b.w * pi.w;

    *(float4*)&sbuf[w][lane * 4] = u;
    __syncwarp();
    if (lane < 8) {
        float s = 0.f;
        #pragma unroll
        for (int i = 0; i < CC; i++) s += sbuf[w][i * 8 + lane];
        out[node * 16 + lane] = logf(s);       // ll0: [n][0][g]
        sbuf[w][128 + lane] = 1.0f / s;
    }
    __syncwarp();
    float4 inv = *(const float4*)&sbuf[w][128 + g0];
    float4 p;
    p.x = u.x * inv.x; p.y = u.y * inv.y; p.z = u.z * inv.z; p.w = u.w * inv.w;
    g_post0[node * 32 + lane] = p;
}

// ---------------- K6: aggregation + layer 1 (warp per node) -----------------
__global__ __launch_bounds__(256) void layer1_k(const int* __restrict__ x,
                                                float* __restrict__ out) {
    __shared__ float sQ [CC * QSTRIDE];
    __shared__ float sB1[CC * BSTRIDE];
    __shared__ __align__(16) float sbuf[8][136];
    for (int i = threadIdx.x; i < CC * QSTRIDE; i += 256) sQ[i]  = g_smQ[i];
    for (int i = threadIdx.x; i < CC * BSTRIDE; i += 256) sB1[i] = g_smB1[i];
    __syncthreads();

    const int lane = threadIdx.x & 31;
    const int w    = threadIdx.x >> 5;
    const int node = blockIdx.x * 8 + w;

    // ---- scatter-mean: gather post0[dst] over this node's CSR list ----
    const int r0 = g_off[node], r1 = g_off[node + 1];
    float4 a0 = {0.f, 0.f, 0.f, 0.f};
    float4 a1 = {0.f, 0.f, 0.f, 0.f};
    int j = r0;
    for (; j + 3 < r1; j += 4) {
        int d0 = g_csr[j], d1 = g_csr[j + 1], d2 = g_csr[j + 2], d3 = g_csr[j + 3];
        float4 v0 = g_post0[d0 * 32 + lane];
        float4 v1 = g_post0[d1 * 32 + lane];
        float4 v2 = g_post0[d2 * 32 + lane];
        float4 v3 = g_post0[d3 * 32 + lane];
        a0.x += v0.x; a0.y += v0.y; a0.z += v0.z; a0.w += v0.w;
        a1.x += v1.x; a1.y += v1.y; a1.z += v1.z; a1.w += v1.w;
        a0.x += v2.x; a0.y += v2.y; a0.z += v2.z; a0.w += v2.w;
        a1.x += v3.x; a1.y += v3.y; a1.z += v3.z; a1.w += v3.w;
    }
    for (; j < r1; j++) {
        float4 v = g_post0[g_csr[j] * 32 + lane];
        a0.x += v.x; a0.y += v.y; a0.z += v.z; a0.w += v.w;
    }
    float inv_deg = 1.0f / fmaxf((float)(r1 - r0), 1.0f);
    float4 ag;
    ag.x = (a0.x + a1.x) * inv_deg;
    ag.y = (a0.y + a1.y) * inv_deg;
    ag.z = (a0.z + a1.z) * inv_deg;
    ag.w = (a0.w + a1.w) * inv_deg;

    *(float4*)&sbuf[w][lane * 4] = ag;         // aggr[l][g] in shared
    __syncwarp();

    // ---- layer 1: S[i,g] = sum_l Q[i,l,g]*aggr[l,g]; post1 = B*S/norm ----
    const int m  = x[node];
    const int i  = lane >> 1;
    const int g0 = (lane & 1) * 4;

    float4 S = {0.f, 0.f, 0.f, 0.f};
    const float* qrow = &sQ[i * QSTRIDE + g0];
    const float* arow = &sbuf[w][g0];
    #pragma unroll
    for (int l = 0; l < CC; l++) {
        float4 q = *(const float4*)(qrow + l * 8);
        float4 a = *(const float4*)(arow + l * 8);
        S.x += q.x * a.x; S.y += q.y * a.y; S.z += q.z * a.z; S.w += q.w * a.w;
    }
    float4 Bn = *(const float4*)&sB1[i * BSTRIDE + m * 8 + g0];
    float4 p;
    p.x = Bn.x * S.x; p.y = Bn.y * S.y; p.z = Bn.z * S.z; p.w = Bn.w * S.w;

    __syncwarp();                               // aggr reads done before overwrite
    *(float4*)&sbuf[w][lane * 4] = p;
    __syncwarp();
    if (lane < 8) {
        float s = 0.f;
        #pragma unroll
        for (int ii = 0; ii < CC; ii++) s += sbuf[w][ii * 8 + lane];
        out[node * 16 + 8 + lane] = logf(s);   // ll1: [n][1][g]
        sbuf[w][128 + lane] = 1.0f / s;
    }
    __syncwarp();
    float4 invn = *(const float4*)&sbuf[w][128 + g0];
    float4 o;
    o.x = p.x * invn.x; o.y = p.y * invn.y; o.z = p.z * invn.z; o.w = p.w * invn.w;
    ((float4*)(out + NN * 16 + node * 128))[lane] = o;   // post1
}

// ---------------- launch ----------------------------------------------------
extern "C" void kernel_launch(void* const* d_in, const int* in_sizes, int n_in,
                              void* d_out, int out_size) {
    const int*   x  = (const int*)d_in[0];
    const int*   ei = (const int*)d_in[1];
    const float* B0 = (const float*)d_in[2];
    const float* Pi = (const float*)d_in[3];
    const float* B1 = (const float*)d_in[4];
    const float* Q  = (const float*)d_in[5];
    float* out = (float*)d_out;

    softmax_k<<<1, 128>>>(B0, Pi, B1, Q);
    zero_k<<<(NN + 255) / 256, 256>>>();
    count_k<<<(EE + 255) / 256, 256>>>(ei);
    bsum_k<<<NB, 1024>>>();
    bscan_k<<<1, 64>>>();
    scan2_k<<<NB, 1024>>>();
    scatter_k<<<(EE + 255) / 256, 256>>>(ei);
    layer0_k<<<NN / 8, 256>>>(x, out);
    layer1_k<<<NN / 8, 256>>>(x, out);
}

// round 6
// speedup vs baseline: 2.7661x; 1.8193x over previous
#include <cuda_runtime.h>
#include <math.h>

#define NN 50000
#define EE 800000
#define CC 16
#define MM 32
#define GG 8

#define BSTRIDE 260   // padded per-c stride for B1 table (bank spread)

// ---------------- device scratch (static: no allocations allowed) ----------
__device__ float g_R  [MM * 128];          // R[m, i, g] = sum_l Q[i,l,g]*P[m,l,g]
__device__ float g_B1 [CC * BSTRIDE];      // softmax(B1) padded
__device__ float g_ll0[MM * GG];           // ll0 per symbol
__device__ int   g_hist[NN * MM];          // neighbor-symbol histogram (zero-init,
                                           // node_k restores zeros after reading)

// ---------------- K0: build all tables (single block, 256 threads) ----------
__global__ __launch_bounds__(256) void setup_k(const float* __restrict__ B0,
                                               const float* __restrict__ Pi,
                                               const float* __restrict__ B1,
                                               const float* __restrict__ Q) {
    __shared__ float sB0[CC * 256];    // c*256 + m*8 + g
    __shared__ float sP [MM * 128];    // m*128 + c*8 + g
    __shared__ float sQ [CC * 128];    // i*128 + l*8 + g
    __shared__ float sPi[CC * GG];     // c*8 + g
    const int t = threadIdx.x;

    if (t < 128) {
        const int c = t >> 3, g = t & 7;
        // softmax(B0) over m
        {
            float mx = -1e30f;
            #pragma unroll
            for (int m = 0; m < MM; m++) mx = fmaxf(mx, B0[(c * MM + m) * GG + g]);
            float e[MM]; float s = 0.f;
            #pragma unroll
            for (int m = 0; m < MM; m++) { e[m] = __expf(B0[(c * MM + m) * GG + g] - mx); s += e[m]; }
            float inv = 1.0f / s;
            #pragma unroll
            for (int m = 0; m < MM; m++) sB0[c * 256 + m * 8 + g] = e[m] * inv;
        }
        // softmax(B1) over m -> global padded table
        {
            float mx = -1e30f;
            #pragma unroll
            for (int m = 0; m < MM; m++) mx = fmaxf(mx, B1[(c * MM + m) * GG + g]);
            float e[MM]; float s = 0.f;
            #pragma unroll
            for (int m = 0; m < MM; m++) { e[m] = __expf(B1[(c * MM + m) * GG + g] - mx); s += e[m]; }
            float inv = 1.0f / s;
            #pragma unroll
            for (int m = 0; m < MM; m++) g_B1[c * BSTRIDE + m * 8 + g] = e[m] * inv;
        }
        // softmax(Q) over i (axis 0) for l = c
        {
            const int l = c;
            float mx = -1e30f;
            #pragma unroll
            for (int i = 0; i < CC; i++) mx = fmaxf(mx, Q[(i * CC + l) * GG + g]);
            float e[CC]; float s = 0.f;
            #pragma unroll
            for (int i = 0; i < CC; i++) { e[i] = __expf(Q[(i * CC + l) * GG + g] - mx); s += e[i]; }
            float inv = 1.0f / s;
            #pragma unroll
            for (int i = 0; i < CC; i++) sQ[i * 128 + l * 8 + g] = e[i] * inv;
        }
    }
    if (t < GG) {  // softmax(Pi) over c, per g
        const int g = t;
        float mx = -1e30f;
        #pragma unroll
        for (int c = 0; c < CC; c++) mx = fmaxf(mx, Pi[c * GG + g]);
        float e[CC]; float s = 0.f;
        #pragma unroll
        for (int c = 0; c < CC; c++) { e[c] = __expf(Pi[c * GG + g] - mx); s += e[c]; }
        float inv = 1.0f / s;
        #pragma unroll
        for (int c = 0; c < CC; c++) sPi[c * 8 + g] = e[c] * inv;
    }
    __syncthreads();

    // P[m,c,g] = Pi*B0 normalized over c; ll0tab[m,g] = log(norm).  256 = M*G pairs
    {
        const int m = t >> 3, g = t & 7;
        float u[CC]; float norm = 0.f;
        #pragma unroll
        for (int c = 0; c < CC; c++) {
            u[c] = sPi[c * 8 + g] * sB0[c * 256 + m * 8 + g];
            norm += u[c];
        }
        g_ll0[m * 8 + g] = logf(norm);
        float inv = 1.0f / norm;
        #pragma unroll
        for (int c = 0; c < CC; c++) sP[m * 128 + c * 8 + g] = u[c] * inv;
    }
    __syncthreads();

    // R[m,i,g] = sum_l sQ[i,l,g] * sP[m,l,g]   (4096 entries)
    for (int idx = t; idx < MM * 128; idx += 256) {
        const int m = idx >> 7, ig = idx & 127;
        const int i = ig >> 3, g = ig & 7;
        float s = 0.f;
        #pragma unroll
        for (int l = 0; l < CC; l++)
            s += sQ[i * 128 + l * 8 + g] * sP[m * 128 + l * 8 + g];
        g_R[idx] = s;
    }
}

// ---------------- K1: edge-parallel neighbor-symbol histogram ----------------
__global__ __launch_bounds__(256) void hist_k(const int* __restrict__ ei,
                                              const int* __restrict__ x) {
    const int e = blockIdx.x * 256 + threadIdx.x;
    if (e < EE) {
        const int s = ei[e];
        const int d = ei[EE + e];
        const int m = __ldg(x + d);
        atomicAdd(&g_hist[s * MM + m], 1);
    }
}

// ---------------- K2: per-node output (warp per node) ------------------------
__global__ __launch_bounds__(256) void node_k(const int* __restrict__ x,
                                              float* __restrict__ out) {
    __shared__ float sR [MM * 128];
    __shared__ float sB1[CC * BSTRIDE];
    __shared__ float sll0[MM * GG];
    __shared__ __align__(16) float sbuf[8][136];
    for (int i = threadIdx.x; i < MM * 128;      i += 256) sR[i]  = g_R[i];
    for (int i = threadIdx.x; i < CC * BSTRIDE;  i += 256) sB1[i] = g_B1[i];
    for (int i = threadIdx.x; i < MM * GG;       i += 256) sll0[i] = g_ll0[i];
    __syncthreads();

    const int lane = threadIdx.x & 31;
    const int w    = threadIdx.x >> 5;
    const int node = blockIdx.x * 8 + w;       // N = 6250*8 exactly

    // histogram row: lane owns symbol `lane`; reset to zero for next replay
    const int cnt = g_hist[node * MM + lane];
    g_hist[node * MM + lane] = 0;
    const int deg = __reduce_add_sync(0xffffffffu, cnt);
    unsigned mask = __ballot_sync(0xffffffffu, cnt > 0);

    // S[i,g] = sum over present symbols of cnt_m * R[m,i,g]
    // lane owns (i = lane>>1, g0 = (lane&1)*4)  ->  float index lane*4
    float4 S0 = {0.f, 0.f, 0.f, 0.f};
    float4 S1 = {0.f, 0.f, 0.f, 0.f};
    while (mask) {
        const int l0 = __ffs(mask) - 1; mask &= mask - 1;
        const float c0 = (float)__shfl_sync(0xffffffffu, cnt, l0);
        const float4 r0 = *(const float4*)&sR[l0 * 128 + lane * 4];
        S0.x += c0 * r0.x; S0.y += c0 * r0.y; S0.z += c0 * r0.z; S0.w += c0 * r0.w;
        if (mask) {
            const int l1 = __ffs(mask) - 1; mask &= mask - 1;
            const float c1 = (float)__shfl_sync(0xffffffffu, cnt, l1);
            const float4 r1 = *(const float4*)&sR[l1 * 128 + lane * 4];
            S1.x += c1 * r1.x; S1.y += c1 * r1.y; S1.z += c1 * r1.z; S1.w += c1 * r1.w;
        }
    }
    const float inv_deg = 1.0f / fmaxf((float)deg, 1.0f);
    float4 S;
    S.x = (S0.x + S1.x) * inv_deg;
    S.y = (S0.y + S1.y) * inv_deg;
    S.z = (S0.z + S1.z) * inv_deg;
    S.w = (S0.w + S1.w) * inv_deg;

    const int m  = x[node];
    const int i  = lane >> 1;
    const int g0 = (lane & 1) * 4;

    const float4 Bn = *(const float4*)&sB1[i * BSTRIDE + m * 8 + g0];
    float4 p;
    p.x = Bn.x * S.x; p.y = Bn.y * S.y; p.z = Bn.z * S.z; p.w = Bn.w * S.w;

    *(float4*)&sbuf[w][lane * 4] = p;
    __syncwarp();
    if (lane < 8) {
        float s = 0.f;
        #pragma unroll
        for (int ii = 0; ii < CC; ii++) s += sbuf[w][ii * 8 + lane];
        out[node * 16 + lane]     = sll0[m * 8 + lane];   // ll0
        out[node * 16 + 8 + lane] = logf(s);              // ll1
        sbuf[w][128 + lane] = 1.0f / s;
    }
    __syncwarp();
    const float4 invn = *(const float4*)&sbuf[w][128 + g0];
    float4 o;
    o.x = p.x * invn.x; o.y = p.y * invn.y; o.z = p.z * invn.z; o.w = p.w * invn.w;
    ((float4*)(out + NN * 16 + node * 128))[lane] = o;    // post1
}

// ---------------- launch ----------------------------------------------------
extern "C" void kernel_launch(void* const* d_in, const int* in_sizes, int n_in,
                              void* d_out, int out_size) {
    const int*   x  = (const int*)d_in[0];
    const int*   ei = (const int*)d_in[1];
    const float* B0 = (const float*)d_in[2];
    const float* Pi = (const float*)d_in[3];
    const float* B1 = (const float*)d_in[4];
    const float* Q  = (const float*)d_in[5];
    float* out = (float*)d_out;

    setup_k<<<1, 256>>>(B0, Pi, B1, Q);
    hist_k<<<(EE + 255) / 256, 256>>>(ei, x);
    node_k<<<NN / 8, 256>>>(x, out);
}